// round 15
// baseline (speedup 1.0000x reference)
#include <cuda_runtime.h>
#include <cuda_fp16.h>
#include <math.h>
#include <stdint.h>

// Problem constants
#define BSZ   32
#define LEN   28
#define NNODE 2048
#define EDIM  256
#define HDIM  512
#define MROWS (BSZ*NNODE) // 65536

// GEMM tiling: CTA 128x128, 16 warps (4x4), warp tile 32x32, BK=64
#define BM 128
#define BN 128
#define BK 64
#define NCHUNK (HDIM/BK)    // 8
#define OA  0
#define OW  16384
#define STAGE 32768
#define NSTAGE 3
#define DSMEM (NSTAGE*STAGE) // 98304 -> 2 CTAs/SM
#define NTHREADS 512

// ---------------------------------------------------------------------------
// Device scratch (h carried as plain fp16)
// ---------------------------------------------------------------------------
__device__ __half g_ah[(size_t)MROWS * HDIM];
__device__ __half g_zh[(size_t)MROWS * HDIM];
__device__ __half g_w1[3 * HDIM * HDIM];
__device__ __half g_w2[3 * HDIM * HDIM];
__device__ float g_bvec[MROWS];
__device__ float g_gvec[MROWS];

// ---------------------------------------------------------------------------
// PTX helpers
// ---------------------------------------------------------------------------
__device__ __forceinline__ uint32_t smem_u32(const void* p) {
    uint32_t a;
    asm("{ .reg .u64 t; cvta.to.shared.u64 t, %1; cvt.u32.u64 %0, t; }" : "=r"(a) : "l"(p));
    return a;
}
__device__ __forceinline__ void cp16(uint32_t dst, const void* src) {
    asm volatile("cp.async.cg.shared.global [%0], [%1], 16;" :: "r"(dst), "l"(src));
}
#define CP_COMMIT() asm volatile("cp.async.commit_group;" ::: "memory")
#define CP_WAIT(n)  asm volatile("cp.async.wait_group %0;" :: "n"(n) : "memory")

__device__ __forceinline__ void ldsm_x4(uint32_t r[4], uint32_t addr) {
    asm volatile("ldmatrix.sync.aligned.m8n8.x4.shared.b16 {%0,%1,%2,%3}, [%4];"
        : "=r"(r[0]), "=r"(r[1]), "=r"(r[2]), "=r"(r[3]) : "r"(addr));
}
__device__ __forceinline__ void mma_f16(float c[4], const uint32_t a[4], const uint32_t b[2]) {
    asm volatile("mma.sync.aligned.m16n8k16.row.col.f32.f16.f16.f32 "
        "{%0,%1,%2,%3}, {%4,%5,%6,%7}, {%8,%9}, {%0,%1,%2,%3};"
        : "+f"(c[0]), "+f"(c[1]), "+f"(c[2]), "+f"(c[3])
        : "r"(a[0]), "r"(a[1]), "r"(a[2]), "r"(a[3]), "r"(b[0]), "r"(b[1]));
}

// SW128 swizzle, 128B-pitch rows, q = 16B slot index (0..7).
// Algebraically identical to off ^ ((off>>3)&0x70) for q<8:
//   (off>>3)&0x70 == (row&7)<<4 (bits 4..6 only), so
//   swz = row*128 + (((q ^ row) & 7) << 4)
__device__ __forceinline__ uint32_t swz128(int row, int q) {
    return (uint32_t)(row * 128 + (((q ^ row) & 7) << 4));
}

// ---------------------------------------------------------------------------
// Weight conversion: fp32 -> fp16
// ---------------------------------------------------------------------------
__global__ __launch_bounds__(256) void wconv_kernel(const float* __restrict__ W1,
                                                    const float* __restrict__ W2)
{
    const int i = blockIdx.x * 256 + threadIdx.x;
    if (i >= 3 * HDIM * HDIM) return;
    g_w1[i] = __float2half_rn(W1[i]);
    g_w2[i] = __float2half_rn(W2[i]);
}

// ---------------------------------------------------------------------------
// Stage A: ts GEMM (K=28) + concat node_emb ; writes fp16 h
// ---------------------------------------------------------------------------
__global__ __launch_bounds__(256) void ts_kernel(
    const float* __restrict__ x_node,
    const float* __restrict__ node_emb,
    const float* __restrict__ W_ts,
    const float* __restrict__ b_ts)
{
    __shared__ float sW[EDIM * LEN];
    __shared__ float sF[64 * LEN];

    const int rowBase = blockIdx.x * 64;
    const int bidx  = rowBase >> 11;
    const int nBase = rowBase & 2047;
    const int tid = threadIdx.x;

    for (int i = tid; i < EDIM * LEN; i += 256) sW[i] = W_ts[i];
    for (int idx = tid; idx < 64 * LEN; idx += 256) {
        int l = idx >> 6;
        int i = idx & 63;
        sF[i * LEN + l] = x_node[((size_t)(bidx * LEN + l)) * NNODE + nBase + i];
    }
    __syncthreads();

    const int e = tid;
    const float bias = b_ts[e];
    const float* wrow = &sW[e * LEN];

    for (int i = 0; i < 64; i++) {
        float acc = bias;
        #pragma unroll
        for (int l = 0; l < LEN; l++)
            acc = fmaf(sF[i * LEN + l], wrow[l], acc);
        const size_t r = (size_t)(rowBase + i) * HDIM;
        g_ah[r + e]        = __float2half_rn(acc);
        g_ah[r + EDIM + e] = __float2half_rn(node_emb[(size_t)(nBase + i) * EDIM + e]);
    }
}

// ---------------------------------------------------------------------------
// Single-term fp16 GEMM on mma.sync: C = A @ W^T + bias [+ R] [relu]
// CTA 128x128, 16 warps (4x4), warp tile 32x32, BK=64, 3-stage cp.async,
// SW128 swizzle (simplified form), 2 CTAs/SM. fp32 staging epilogue,
// vectorized phase 2.
// ---------------------------------------------------------------------------
template <bool RELU, bool ADDIN>
__global__ void __launch_bounds__(NTHREADS, 2) gemm_mma(
    const __half* __restrict__ A,
    const __half* __restrict__ W,
    const float* __restrict__ bias,
    const __half* __restrict__ R,
    __half* __restrict__ outp)
{
    extern __shared__ char dsm[];
    __shared__ float sbias[BN];

    const int tid = threadIdx.x;
    const int wid = tid >> 5;
    const int lane = tid & 31;
    const int warp_m = wid & 3;
    const int warp_n = wid >> 2;
    const int rowBase = blockIdx.y * BM;
    const int colBase = blockIdx.x * BN;

    if (tid < BN) sbias[tid] = bias[colBase + tid];

    const uint32_t sb = smem_u32(dsm);

    float c[2][4][4];
    #pragma unroll
    for (int i = 0; i < 2; i++)
        #pragma unroll
        for (int j = 0; j < 4; j++)
            #pragma unroll
            for (int k = 0; k < 4; k++) c[i][j][k] = 0.f;

    // ---- chunk loader: 1024 16B-units per array, 2 per thread per array ----
    auto load_chunk = [&](int cidx, int s) {
        const uint32_t base = sb + (uint32_t)s * STAGE;
        const int kk = cidx * BK;
        #pragma unroll
        for (int j = 0; j < 2; j++) {
            const int u = tid + j * NTHREADS;
            const int row = u >> 3;
            const int q = u & 7;
            const uint32_t doff = swz128(row, q);
            const int eoff = kk + q * 8;       // 8 fp16 per 16B
            cp16(base + OA + doff, A + (size_t)(rowBase + row) * HDIM + eoff);
            cp16(base + OW + doff, W + (size_t)(colBase + row) * HDIM + eoff);
        }
        CP_COMMIT();
    };

    // ---- fragment addressing ----
    const int ra  = warp_m * 32 + (lane & 15);
    const int qa  = lane >> 4;                        // 0/1
    const int rb  = warp_n * 32 + ((lane >> 4) & 1) * 8 + (lane & 7);
    const int qb  = (lane >> 3) & 1;                  // 0/1

    auto compute = [&](int s) {
        const uint32_t base = sb + (uint32_t)s * STAGE;
        #pragma unroll
        for (int ks = 0; ks < 4; ks++) {
            uint32_t wv[2][4];
            ldsm_x4(wv[0], base + OW + swz128(rb, qb + 2 * ks));
            ldsm_x4(wv[1], base + OW + swz128(rb + 16, qb + 2 * ks));
            uint32_t a[2][4];
            ldsm_x4(a[0], base + OA + swz128(ra, qa + 2 * ks));
            ldsm_x4(a[1], base + OA + swz128(ra + 16, qa + 2 * ks));
            #pragma unroll
            for (int mf = 0; mf < 2; mf++)
                #pragma unroll
                for (int nf = 0; nf < 4; nf++)
                    mma_f16(c[mf][nf], a[mf], &wv[nf >> 1][(nf & 1) * 2]);
        }
    };

    // ---- multistage mainloop: 8 chunks, 1 sync per chunk ----
    load_chunk(0, 0);
    load_chunk(1, 1);
    CP_WAIT(1);            // chunk 0 landed
    __syncthreads();

    for (int m = 0; m < NCHUNK; m++) {
        if (m + 2 < NCHUNK) load_chunk(m + 2, (m + 2) % NSTAGE);
        compute(m % NSTAGE);
        if (m + 2 < NCHUNK)      { CP_WAIT(1); }   // chunk m+1 landed
        else if (m + 1 < NCHUNK) { CP_WAIT(0); }
        __syncthreads();
    }

    // ---- epilogue phase 1: raw fragments -> fp32 smem staging (coalesce) ----
    float* stg = (float*)dsm;   // 128 x 132 fp32 = 67584 B
    #pragma unroll
    for (int mf = 0; mf < 2; mf++) {
        #pragma unroll
        for (int nf = 0; nf < 4; nf++) {
            const int r0 = warp_m * 32 + mf * 16 + (lane >> 2);
            const int cc = warp_n * 32 + nf * 8 + 2 * (lane & 3);
            *(float2*)&stg[(size_t)r0 * 132 + cc]       = make_float2(c[mf][nf][0], c[mf][nf][1]);
            *(float2*)&stg[(size_t)(r0 + 8) * 132 + cc] = make_float2(c[mf][nf][2], c[mf][nf][3]);
        }
    }
    __syncthreads();

    // ---- epilogue phase 2: vectorized (column pairs, half2 gmem ops) ----
    #pragma unroll
    for (int j = 0; j < 16; j++) {
        const int u = tid + j * NTHREADS;      // 0..8191 = 128 rows x 64 pairs
        const int row = u >> 6;
        const int cp  = u & 63;                // column-pair index
        const float2 cv = *(const float2*)&stg[(size_t)row * 132 + cp * 2];
        const float2 bv = *(const float2*)&sbias[cp * 2];
        float v0 = cv.x + bv.x;
        float v1 = cv.y + bv.y;
        const size_t gi = (size_t)(rowBase + row) * HDIM + colBase + cp * 2;
        if (ADDIN) {
            const float2 fr2 = __half22float2(*(const __half2*)(R + gi));
            v0 += fr2.x; v1 += fr2.y;
        }
        if (RELU) { v0 = fmaxf(v0, 0.f); v1 = fmaxf(v1, 0.f); }
        *(__half2*)(outp + gi) = __floats2half2_rn(v0, v1);
    }
}

// ---------------------------------------------------------------------------
// Stage C: b = sigmoid(h@Wb^T+bb), g = sigmoid(h@Wg^T+bg)
// ---------------------------------------------------------------------------
__global__ __launch_bounds__(256) void bg_kernel(
    const float* __restrict__ Wb, const float* __restrict__ bbias,
    const float* __restrict__ Wg, const float* __restrict__ gbias)
{
    __shared__ float sWb[HDIM];
    __shared__ float sWg[HDIM];
    const int tid = threadIdx.x;
    for (int i = tid; i < HDIM; i += 256) { sWb[i] = Wb[i]; sWg[i] = Wg[i]; }
    __syncthreads();

    const int warp = tid >> 5;
    const int lane = tid & 31;
    const size_t row = (size_t)blockIdx.x * 8 + warp;
    const __half* hr = g_ah + row * HDIM;

    float accb = 0.f, accg = 0.f;
    #pragma unroll
    for (int i = 0; i < HDIM / 32; i++) {
        const int idx = lane + i * 32;
        const float hv = __half2float(hr[idx]);
        accb = fmaf(hv, sWb[idx], accb);
        accg = fmaf(hv, sWg[idx], accg);
    }
    #pragma unroll
    for (int o = 16; o; o >>= 1) {
        accb += __shfl_xor_sync(0xFFFFFFFFu, accb, o);
        accg += __shfl_xor_sync(0xFFFFFFFFu, accg, o);
    }
    if (lane == 0) {
        g_bvec[row] = 1.f / (1.f + expf(-(accb + bbias[0])));
        g_gvec[row] = 1.f / (1.f + expf(-(accg + gbias[0])));
    }
}

// ---------------------------------------------------------------------------
// Stage D: SIR reconstruction + 28-step scan
// ---------------------------------------------------------------------------
__global__ __launch_bounds__(256) void sim_kernel(
    const float* __restrict__ x_state, float* __restrict__ out)
{
    const size_t r = (size_t)blockIdx.x * blockDim.x + threadIdx.x;
    const int b = (int)(r >> 11);
    const int n = (int)(r & 2047);

    const float beta = g_bvec[r];
    const float g    = g_gvec[r];
    const float decay = expf(-g);
    const float inv_g = 1.f / g;

    const float* xs = x_state + ((size_t)b * LEN * NNODE + n) * 3;
    const int TSTRIDE = NNODE * 3;

    float Iprev = xs[0 * TSTRIDE + 1];
    float acc = 0.f;
    #pragma unroll
    for (int t = 1; t <= LEN - 1; t++) {
        const float Icur = xs[t * TSTRIDE + 1];
        const float iin = fmaxf((Icur - Iprev) * inv_g + Iprev, 0.f);
        acc = fmaf(acc, decay, iin);
        Iprev = Icur;
    }

    const float Npop  = xs[(LEN - 1) * TSTRIDE + 2];
    const float R_Tm1 = Npop - xs[(LEN - 2) * TSTRIDE + 0];
    const float I_Tm1 = decay * acc;
    const float S_Tm1 = Npop - I_Tm1 - R_Tm1;
    const float Iin0  = beta * S_Tm1 * I_Tm1 / Npop;

    float S = S_Tm1 - Iin0;
    float I = decay * (I_Tm1 + Iin0);

    float* op = out + (size_t)b * LEN * NNODE + n;
    #pragma unroll
    for (int t = 0; t < LEN; t++) {
        const float Iin = beta * S * I / Npop;
        S -= Iin;
        const float Rin = g * I;
        I = decay * (I + Iin);
        op[(size_t)t * NNODE] = Rin;
    }
}

// ---------------------------------------------------------------------------
extern "C" void kernel_launch(void* const* d_in, const int* in_sizes, int n_in,
                              void* d_out, int out_size)
{
    (void)in_sizes; (void)n_in; (void)out_size;
    const float* x_node   = (const float*)d_in[0];
    const float* x_state  = (const float*)d_in[1];
    const float* node_emb = (const float*)d_in[2];
    const float* W_ts     = (const float*)d_in[3];
    const float* b_ts     = (const float*)d_in[4];
    const float* enc_W1   = (const float*)d_in[5];
    const float* enc_b1   = (const float*)d_in[6];
    const float* enc_W2   = (const float*)d_in[7];
    const float* enc_b2   = (const float*)d_in[8];
    const float* Wb       = (const float*)d_in[9];
    const float* bb       = (const float*)d_in[10];
    const float* Wg       = (const float*)d_in[11];
    const float* bg       = (const float*)d_in[12];
    float* out = (float*)d_out;

    __half *ah, *zh, *w1, *w2;
    cudaGetSymbolAddress((void**)&ah, g_ah);
    cudaGetSymbolAddress((void**)&zh, g_zh);
    cudaGetSymbolAddress((void**)&w1, g_w1);
    cudaGetSymbolAddress((void**)&w2, g_w2);

    cudaFuncSetAttribute(gemm_mma<true,  false>, cudaFuncAttributeMaxDynamicSharedMemorySize, DSMEM);
    cudaFuncSetAttribute(gemm_mma<false, true >, cudaFuncAttributeMaxDynamicSharedMemorySize, DSMEM);

    // weights -> fp16
    wconv_kernel<<<(3 * HDIM * HDIM + 255) / 256, 256>>>(enc_W1, enc_W2);

    // Stage A
    ts_kernel<<<MROWS / 64, 256>>>(x_node, node_emb, W_ts, b_ts);

    // Stage B: 3 residual layers on tensor cores
    const dim3 grid(HDIM / BN, MROWS / BM);   // (4, 512)
    for (int l = 0; l < 3; l++) {
        const __half* W1 = w1 + (size_t)l * HDIM * HDIM;
        const __half* W2 = w2 + (size_t)l * HDIM * HDIM;
        const float* B1 = enc_b1 + (size_t)l * HDIM;
        const float* B2 = enc_b2 + (size_t)l * HDIM;

        // z = relu(h @ W1^T + b1)
        gemm_mma<true, false><<<grid, NTHREADS, DSMEM>>>(ah, W1, B1, nullptr, zh);
        // h = h + z @ W2^T + b2
        gemm_mma<false, true><<<grid, NTHREADS, DSMEM>>>(zh, W2, B2, ah, ah);
    }

    // Stage C + D
    bg_kernel<<<MROWS / 8, 256>>>(Wb, bb, Wg, bg);
    sim_kernel<<<MROWS / 256, 256>>>(x_state, out);
}

// round 16
// speedup vs baseline: 1.4297x; 1.4297x over previous
#include <cuda_runtime.h>
#include <cuda_fp16.h>
#include <math.h>
#include <stdint.h>

// Problem constants
#define BSZ   32
#define LEN   28
#define NNODE 2048
#define EDIM  256
#define HDIM  512
#define MROWS (BSZ*NNODE) // 65536

// GEMM tiling: CTA 128x128, 8 warps (2x4), warp tile 64x32, BK=64
#define BM 128
#define BN 128
#define BK 64
#define NCHUNK (HDIM/BK)    // 8
#define OA  0
#define OW  16384
#define STAGE 32768
#define NSTAGE 3
#define DSMEM (NSTAGE*STAGE) // 98304 -> 2 CTAs/SM
#define NTHREADS 256

// ---------------------------------------------------------------------------
// Device scratch (h carried as plain fp16)
// ---------------------------------------------------------------------------
__device__ __half g_ah[(size_t)MROWS * HDIM];
__device__ __half g_zh[(size_t)MROWS * HDIM];
__device__ __half g_w1[3 * HDIM * HDIM];
__device__ __half g_w2[3 * HDIM * HDIM];
__device__ float g_bvec[MROWS];
__device__ float g_gvec[MROWS];

// ---------------------------------------------------------------------------
// PTX helpers
// ---------------------------------------------------------------------------
__device__ __forceinline__ uint32_t smem_u32(const void* p) {
    uint32_t a;
    asm("{ .reg .u64 t; cvta.to.shared.u64 t, %1; cvt.u32.u64 %0, t; }" : "=r"(a) : "l"(p));
    return a;
}
__device__ __forceinline__ void cp16(uint32_t dst, const void* src) {
    asm volatile("cp.async.cg.shared.global [%0], [%1], 16;" :: "r"(dst), "l"(src));
}
#define CP_COMMIT() asm volatile("cp.async.commit_group;" ::: "memory")
#define CP_WAIT(n)  asm volatile("cp.async.wait_group %0;" :: "n"(n) : "memory")

__device__ __forceinline__ void ldsm_x4(uint32_t r[4], uint32_t addr) {
    asm volatile("ldmatrix.sync.aligned.m8n8.x4.shared.b16 {%0,%1,%2,%3}, [%4];"
        : "=r"(r[0]), "=r"(r[1]), "=r"(r[2]), "=r"(r[3]) : "r"(addr));
}
__device__ __forceinline__ void mma_f16(float c[4], const uint32_t a[4], const uint32_t b[2]) {
    asm volatile("mma.sync.aligned.m16n8k16.row.col.f32.f16.f16.f32 "
        "{%0,%1,%2,%3}, {%4,%5,%6,%7}, {%8,%9}, {%0,%1,%2,%3};"
        : "+f"(c[0]), "+f"(c[1]), "+f"(c[2]), "+f"(c[3])
        : "r"(a[0]), "r"(a[1]), "r"(a[2]), "r"(a[3]), "r"(b[0]), "r"(b[1]));
}

// SW128 swizzle, 128B-pitch rows, q = 16B slot index (0..7) — ORIGINAL XOR form
__device__ __forceinline__ uint32_t swz128(int row, int q) {
    const uint32_t off = (uint32_t)(row * 128 + q * 16);
    return off ^ ((off >> 3) & 0x70u);
}

// ---------------------------------------------------------------------------
// Weight conversion: fp32 -> fp16
// ---------------------------------------------------------------------------
__global__ __launch_bounds__(256) void wconv_kernel(const float* __restrict__ W1,
                                                    const float* __restrict__ W2)
{
    const int i = blockIdx.x * 256 + threadIdx.x;
    if (i >= 3 * HDIM * HDIM) return;
    g_w1[i] = __float2half_rn(W1[i]);
    g_w2[i] = __float2half_rn(W2[i]);
}

// ---------------------------------------------------------------------------
// Stage A: ts GEMM (K=28) + concat node_emb ; writes fp16 h
// ---------------------------------------------------------------------------
__global__ __launch_bounds__(256) void ts_kernel(
    const float* __restrict__ x_node,
    const float* __restrict__ node_emb,
    const float* __restrict__ W_ts,
    const float* __restrict__ b_ts)
{
    __shared__ float sW[EDIM * LEN];
    __shared__ float sF[64 * LEN];

    const int rowBase = blockIdx.x * 64;
    const int bidx  = rowBase >> 11;
    const int nBase = rowBase & 2047;
    const int tid = threadIdx.x;

    for (int i = tid; i < EDIM * LEN; i += 256) sW[i] = W_ts[i];
    for (int idx = tid; idx < 64 * LEN; idx += 256) {
        int l = idx >> 6;
        int i = idx & 63;
        sF[i * LEN + l] = x_node[((size_t)(bidx * LEN + l)) * NNODE + nBase + i];
    }
    __syncthreads();

    const int e = tid;
    const float bias = b_ts[e];
    const float* wrow = &sW[e * LEN];

    for (int i = 0; i < 64; i++) {
        float acc = bias;
        #pragma unroll
        for (int l = 0; l < LEN; l++)
            acc = fmaf(sF[i * LEN + l], wrow[l], acc);
        const size_t r = (size_t)(rowBase + i) * HDIM;
        g_ah[r + e]        = __float2half_rn(acc);
        g_ah[r + EDIM + e] = __float2half_rn(node_emb[(size_t)(nBase + i) * EDIM + e]);
    }
}

// ---------------------------------------------------------------------------
// Single-term fp16 GEMM on mma.sync: C = A @ W^T + bias [+ R] [relu]
// CTA 128x128, 8 warps (2x4), warp tile 64x32, BK=64, 3-stage cp.async,
// SW128 swizzle (XOR form), 2 CTAs/SM. fp32 staging epilogue, vectorized
// phase 2.
// ---------------------------------------------------------------------------
template <bool RELU, bool ADDIN>
__global__ void __launch_bounds__(NTHREADS, 2) gemm_mma(
    const __half* __restrict__ A,
    const __half* __restrict__ W,
    const float* __restrict__ bias,
    const __half* __restrict__ R,
    __half* __restrict__ outp)
{
    extern __shared__ char dsm[];
    __shared__ float sbias[BN];

    const int tid = threadIdx.x;
    const int wid = tid >> 5;
    const int lane = tid & 31;
    const int warp_m = wid & 1;          // 0..1 -> 64-row halves
    const int warp_n = wid >> 1;         // 0..3 -> 32-col quarters
    const int rowBase = blockIdx.y * BM;
    const int colBase = blockIdx.x * BN;

    if (tid < BN) sbias[tid] = bias[colBase + tid];

    const uint32_t sb = smem_u32(dsm);

    float c[4][4][4];
    #pragma unroll
    for (int i = 0; i < 4; i++)
        #pragma unroll
        for (int j = 0; j < 4; j++)
            #pragma unroll
            for (int k = 0; k < 4; k++) c[i][j][k] = 0.f;

    // ---- chunk loader: 1024 16B-units per array, 4 per thread per array ----
    auto load_chunk = [&](int cidx, int s) {
        const uint32_t base = sb + (uint32_t)s * STAGE;
        const int kk = cidx * BK;
        #pragma unroll
        for (int j = 0; j < 4; j++) {
            const int u = tid + j * NTHREADS;
            const int row = u >> 3;
            const int q = u & 7;
            const uint32_t doff = swz128(row, q);
            const int eoff = kk + q * 8;       // 8 fp16 per 16B
            cp16(base + OA + doff, A + (size_t)(rowBase + row) * HDIM + eoff);
            cp16(base + OW + doff, W + (size_t)(colBase + row) * HDIM + eoff);
        }
        CP_COMMIT();
    };

    // ---- fragment addressing ----
    const int ra  = warp_m * 64 + (lane & 15);
    const int qa  = lane >> 4;                        // 0/1
    const int rb  = warp_n * 32 + ((lane >> 4) & 1) * 8 + (lane & 7);
    const int qb  = (lane >> 3) & 1;                  // 0/1

    auto compute = [&](int s) {
        const uint32_t base = sb + (uint32_t)s * STAGE;
        #pragma unroll
        for (int ks = 0; ks < 4; ks++) {
            uint32_t wv[2][4];
            ldsm_x4(wv[0], base + OW + swz128(rb, qb + 2 * ks));
            ldsm_x4(wv[1], base + OW + swz128(rb + 16, qb + 2 * ks));
            uint32_t a[4][4];
            #pragma unroll
            for (int mf = 0; mf < 4; mf++)
                ldsm_x4(a[mf], base + OA + swz128(ra + mf * 16, qa + 2 * ks));
            #pragma unroll
            for (int mf = 0; mf < 4; mf++)
                #pragma unroll
                for (int nf = 0; nf < 4; nf++)
                    mma_f16(c[mf][nf], a[mf], &wv[nf >> 1][(nf & 1) * 2]);
        }
    };

    // ---- multistage mainloop: 8 chunks, 1 sync per chunk ----
    load_chunk(0, 0);
    load_chunk(1, 1);
    CP_WAIT(1);            // chunk 0 landed
    __syncthreads();

    for (int m = 0; m < NCHUNK; m++) {
        if (m + 2 < NCHUNK) load_chunk(m + 2, (m + 2) % NSTAGE);
        compute(m % NSTAGE);
        if (m + 2 < NCHUNK)      { CP_WAIT(1); }   // chunk m+1 landed
        else if (m + 1 < NCHUNK) { CP_WAIT(0); }
        __syncthreads();
    }

    // ---- epilogue phase 1: raw fragments -> fp32 smem staging (coalesce) ----
    float* stg = (float*)dsm;   // 128 x 132 fp32 = 67584 B
    #pragma unroll
    for (int mf = 0; mf < 4; mf++) {
        #pragma unroll
        for (int nf = 0; nf < 4; nf++) {
            const int r0 = warp_m * 64 + mf * 16 + (lane >> 2);
            const int cc = warp_n * 32 + nf * 8 + 2 * (lane & 3);
            *(float2*)&stg[(size_t)r0 * 132 + cc]       = make_float2(c[mf][nf][0], c[mf][nf][1]);
            *(float2*)&stg[(size_t)(r0 + 8) * 132 + cc] = make_float2(c[mf][nf][2], c[mf][nf][3]);
        }
    }
    __syncthreads();

    // ---- epilogue phase 2: vectorized (column pairs, half2 gmem ops) ----
    #pragma unroll
    for (int j = 0; j < 32; j++) {
        const int u = tid + j * NTHREADS;      // 0..8191 = 128 rows x 64 pairs
        const int row = u >> 6;
        const int cp  = u & 63;                // column-pair index
        const float2 cv = *(const float2*)&stg[(size_t)row * 132 + cp * 2];
        const float2 bv = *(const float2*)&sbias[cp * 2];
        float v0 = cv.x + bv.x;
        float v1 = cv.y + bv.y;
        const size_t gi = (size_t)(rowBase + row) * HDIM + colBase + cp * 2;
        if (ADDIN) {
            const float2 fr2 = __half22float2(*(const __half2*)(R + gi));
            v0 += fr2.x; v1 += fr2.y;
        }
        if (RELU) { v0 = fmaxf(v0, 0.f); v1 = fmaxf(v1, 0.f); }
        *(__half2*)(outp + gi) = __floats2half2_rn(v0, v1);
    }
}

// ---------------------------------------------------------------------------
// Stage C: b = sigmoid(h@Wb^T+bb), g = sigmoid(h@Wg^T+bg)
// ---------------------------------------------------------------------------
__global__ __launch_bounds__(256) void bg_kernel(
    const float* __restrict__ Wb, const float* __restrict__ bbias,
    const float* __restrict__ Wg, const float* __restrict__ gbias)
{
    __shared__ float sWb[HDIM];
    __shared__ float sWg[HDIM];
    const int tid = threadIdx.x;
    for (int i = tid; i < HDIM; i += 256) { sWb[i] = Wb[i]; sWg[i] = Wg[i]; }
    __syncthreads();

    const int warp = tid >> 5;
    const int lane = tid & 31;
    const size_t row = (size_t)blockIdx.x * 8 + warp;
    const __half* hr = g_ah + row * HDIM;

    float accb = 0.f, accg = 0.f;
    #pragma unroll
    for (int i = 0; i < HDIM / 32; i++) {
        const int idx = lane + i * 32;
        const float hv = __half2float(hr[idx]);
        accb = fmaf(hv, sWb[idx], accb);
        accg = fmaf(hv, sWg[idx], accg);
    }
    #pragma unroll
    for (int o = 16; o; o >>= 1) {
        accb += __shfl_xor_sync(0xFFFFFFFFu, accb, o);
        accg += __shfl_xor_sync(0xFFFFFFFFu, accg, o);
    }
    if (lane == 0) {
        g_bvec[row] = 1.f / (1.f + expf(-(accb + bbias[0])));
        g_gvec[row] = 1.f / (1.f + expf(-(accg + gbias[0])));
    }
}

// ---------------------------------------------------------------------------
// Stage D: SIR reconstruction + 28-step scan
// ---------------------------------------------------------------------------
__global__ __launch_bounds__(256) void sim_kernel(
    const float* __restrict__ x_state, float* __restrict__ out)
{
    const size_t r = (size_t)blockIdx.x * blockDim.x + threadIdx.x;
    const int b = (int)(r >> 11);
    const int n = (int)(r & 2047);

    const float beta = g_bvec[r];
    const float g    = g_gvec[r];
    const float decay = expf(-g);
    const float inv_g = 1.f / g;

    const float* xs = x_state + ((size_t)b * LEN * NNODE + n) * 3;
    const int TSTRIDE = NNODE * 3;

    float Iprev = xs[0 * TSTRIDE + 1];
    float acc = 0.f;
    #pragma unroll
    for (int t = 1; t <= LEN - 1; t++) {
        const float Icur = xs[t * TSTRIDE + 1];
        const float iin = fmaxf((Icur - Iprev) * inv_g + Iprev, 0.f);
        acc = fmaf(acc, decay, iin);
        Iprev = Icur;
    }

    const float Npop  = xs[(LEN - 1) * TSTRIDE + 2];
    const float R_Tm1 = Npop - xs[(LEN - 2) * TSTRIDE + 0];
    const float I_Tm1 = decay * acc;
    const float S_Tm1 = Npop - I_Tm1 - R_Tm1;
    const float Iin0  = beta * S_Tm1 * I_Tm1 / Npop;

    float S = S_Tm1 - Iin0;
    float I = decay * (I_Tm1 + Iin0);

    float* op = out + (size_t)b * LEN * NNODE + n;
    #pragma unroll
    for (int t = 0; t < LEN; t++) {
        const float Iin = beta * S * I / Npop;
        S -= Iin;
        const float Rin = g * I;
        I = decay * (I + Iin);
        op[(size_t)t * NNODE] = Rin;
    }
}

// ---------------------------------------------------------------------------
extern "C" void kernel_launch(void* const* d_in, const int* in_sizes, int n_in,
                              void* d_out, int out_size)
{
    (void)in_sizes; (void)n_in; (void)out_size;
    const float* x_node   = (const float*)d_in[0];
    const float* x_state  = (const float*)d_in[1];
    const float* node_emb = (const float*)d_in[2];
    const float* W_ts     = (const float*)d_in[3];
    const float* b_ts     = (const float*)d_in[4];
    const float* enc_W1   = (const float*)d_in[5];
    const float* enc_b1   = (const float*)d_in[6];
    const float* enc_W2   = (const float*)d_in[7];
    const float* enc_b2   = (const float*)d_in[8];
    const float* Wb       = (const float*)d_in[9];
    const float* bb       = (const float*)d_in[10];
    const float* Wg       = (const float*)d_in[11];
    const float* bg       = (const float*)d_in[12];
    float* out = (float*)d_out;

    __half *ah, *zh, *w1, *w2;
    cudaGetSymbolAddress((void**)&ah, g_ah);
    cudaGetSymbolAddress((void**)&zh, g_zh);
    cudaGetSymbolAddress((void**)&w1, g_w1);
    cudaGetSymbolAddress((void**)&w2, g_w2);

    cudaFuncSetAttribute(gemm_mma<true,  false>, cudaFuncAttributeMaxDynamicSharedMemorySize, DSMEM);
    cudaFuncSetAttribute(gemm_mma<false, true >, cudaFuncAttributeMaxDynamicSharedMemorySize, DSMEM);

    // weights -> fp16
    wconv_kernel<<<(3 * HDIM * HDIM + 255) / 256, 256>>>(enc_W1, enc_W2);

    // Stage A
    ts_kernel<<<MROWS / 64, 256>>>(x_node, node_emb, W_ts, b_ts);

    // Stage B: 3 residual layers on tensor cores
    const dim3 grid(HDIM / BN, MROWS / BM);   // (4, 512)
    for (int l = 0; l < 3; l++) {
        const __half* W1 = w1 + (size_t)l * HDIM * HDIM;
        const __half* W2 = w2 + (size_t)l * HDIM * HDIM;
        const float* B1 = enc_b1 + (size_t)l * HDIM;
        const float* B2 = enc_b2 + (size_t)l * HDIM;

        // z = relu(h @ W1^T + b1)
        gemm_mma<true, false><<<grid, NTHREADS, DSMEM>>>(ah, W1, B1, nullptr, zh);
        // h = h + z @ W2^T + b2
        gemm_mma<false, true><<<grid, NTHREADS, DSMEM>>>(zh, W2, B2, ah, ah);
    }

    // Stage C + D
    bg_kernel<<<MROWS / 8, 256>>>(Wb, bb, Wg, bg);
    sim_kernel<<<MROWS / 256, 256>>>(x_state, out);
}